// round 1
// baseline (speedup 1.0000x reference)
#include <cuda_runtime.h>

// Word2DM loss:
//   sims(b, X) = || Bt_b^T X ||_F^2 = <Gt_b, Gx>_F  where G = B B^T (contract over m)
//   loss_b = log1p(exp(-sims_ctx)) + sum_k log1p(exp(+sims_neg_k))
//   out = mean_b loss_b
//
// Shapes: VOCAB x 400 weight tables (n=m=20), B=16384, K=10.

#define NDIM 20
#define MDIM 20
#define ROWF (NDIM * MDIM)        // 400 floats per vocab row
#define ROW4 (ROWF / 4)           // 100 float4 per row
#define SPB  16                   // samples per block
#define TPB  (SPB * NDIM)         // 320 threads

__global__ void w2dm_zero(float* out) { out[0] = 0.0f; }

__global__ __launch_bounds__(TPB) void w2dm_kernel(
    const float* __restrict__ Wt,
    const float* __restrict__ Wc,
    const int*   __restrict__ tgt,
    const int*   __restrict__ ctx,
    const int*   __restrict__ neg,
    float*       __restrict__ out,
    int batch, int kneg, float inv_batch)
{
    __shared__ float stage[SPB][ROWF];   // gathered rows for 16 samples
    __shared__ float part[SPB][NDIM];    // per-thread sims partials
    __shared__ float lossbuf[SPB];

    const int tid = threadIdx.x;
    const int s   = tid / NDIM;          // local sample 0..15
    const int n   = tid % NDIM;          // row index 0..19
    const int sample0 = blockIdx.x * SPB;
    const int my_sample = sample0 + s;
    const bool valid = (my_sample < batch);

    // ---------------- stage Bt rows (coalesced float4) ----------------
    for (int i = tid; i < SPB * ROW4; i += TPB) {
        const int ss  = i / ROW4;
        const int e4  = i % ROW4;
        const int smp = sample0 + ss;
        if (smp < batch) {
            const float4* src =
                reinterpret_cast<const float4*>(Wt + (size_t)tgt[smp] * ROWF);
            reinterpret_cast<float4*>(stage[ss])[e4] = src[e4];
        } else {
            reinterpret_cast<float4*>(stage[ss])[e4] = make_float4(0.f, 0.f, 0.f, 0.f);
        }
    }
    __syncthreads();

    // own Bt row -> registers
    float b[NDIM];
    #pragma unroll
    for (int j = 0; j < MDIM / 4; j++) {
        float4 v = reinterpret_cast<const float4*>(&stage[s][n * MDIM])[j];
        b[4 * j + 0] = v.x; b[4 * j + 1] = v.y;
        b[4 * j + 2] = v.z; b[4 * j + 3] = v.w;
    }

    // Gt row n in registers: g[n'] = dot(Bt row n, Bt row n')
    float g[NDIM];
    #pragma unroll
    for (int np = 0; np < NDIM; np++) {
        float t = 0.0f;
        #pragma unroll
        for (int j = 0; j < MDIM / 4; j++) {
            float4 v = reinterpret_cast<const float4*>(&stage[s][np * MDIM])[j];
            t += b[4 * j + 0] * v.x + b[4 * j + 1] * v.y
               + b[4 * j + 2] * v.z + b[4 * j + 3] * v.w;
        }
        g[np] = t;
    }

    float loss = 0.0f;   // only meaningful for tid < SPB

    // ---------------- phases: k=0 context, k=1..kneg negatives ----------------
    for (int k = 0; k <= kneg; k++) {
        __syncthreads();   // prior stage reads + part writes complete

        // reducer threads fold the previous phase's partials
        if (k > 0 && tid < SPB) {
            float sims = 0.0f;
            #pragma unroll
            for (int i = 0; i < NDIM; i++) sims += part[tid][i];
            if (sample0 + tid < batch) {
                if (k == 1) loss += log1pf(expf(-sims));   // context term
                else        loss += log1pf(expf(sims));    // negative term
            }
        }

        // stage X rows (context or k-1'th negative)
        for (int i = tid; i < SPB * ROW4; i += TPB) {
            const int ss  = i / ROW4;
            const int e4  = i % ROW4;
            const int smp = sample0 + ss;
            if (smp < batch) {
                const int idx = (k == 0) ? ctx[smp]
                                         : neg[(size_t)smp * kneg + (k - 1)];
                const float4* src =
                    reinterpret_cast<const float4*>(Wc + (size_t)idx * ROWF);
                reinterpret_cast<float4*>(stage[ss])[e4] = src[e4];
            }
        }
        __syncthreads();

        // own X row -> registers
        float x[NDIM];
        #pragma unroll
        for (int j = 0; j < MDIM / 4; j++) {
            float4 v = reinterpret_cast<const float4*>(&stage[s][n * MDIM])[j];
            x[4 * j + 0] = v.x; x[4 * j + 1] = v.y;
            x[4 * j + 2] = v.z; x[4 * j + 3] = v.w;
        }

        // acc = sum_{n'} dot(x_n, x_{n'}) * Gt[n][n']
        float acc = 0.0f;
        #pragma unroll
        for (int np = 0; np < NDIM; np++) {
            float t = 0.0f;
            #pragma unroll
            for (int j = 0; j < MDIM / 4; j++) {
                float4 v = reinterpret_cast<const float4*>(&stage[s][np * MDIM])[j];
                t += x[4 * j + 0] * v.x + x[4 * j + 1] * v.y
                   + x[4 * j + 2] * v.z + x[4 * j + 3] * v.w;
            }
            acc += t * g[np];
        }
        part[s][n] = acc;
    }

    __syncthreads();
    if (tid < SPB) {
        float sims = 0.0f;
        #pragma unroll
        for (int i = 0; i < NDIM; i++) sims += part[tid][i];
        if (sample0 + tid < batch) loss += log1pf(expf(sims));   // last negative
        lossbuf[tid] = loss;
    }
    __syncthreads();
    if (tid == 0) {
        float bs = 0.0f;
        #pragma unroll
        for (int i = 0; i < SPB; i++) bs += lossbuf[i];
        atomicAdd(out, bs * inv_batch);
    }
}

extern "C" void kernel_launch(void* const* d_in, const int* in_sizes, int n_in,
                              void* d_out, int out_size)
{
    const float* Wt  = (const float*)d_in[0];
    const float* Wc  = (const float*)d_in[1];
    const int*   tgt = (const int*)d_in[2];
    const int*   ctx = (const int*)d_in[3];
    const int*   neg = (const int*)d_in[4];
    float*       out = (float*)d_out;

    const int batch = in_sizes[2];
    const int kneg  = in_sizes[4] / batch;
    const float inv_batch = 1.0f / (float)batch;

    w2dm_zero<<<1, 1>>>(out);

    const int grid = (batch + SPB - 1) / SPB;
    w2dm_kernel<<<grid, TPB>>>(Wt, Wc, tgt, ctx, neg, out,
                               batch, kneg, inv_batch);
}

// round 2
// speedup vs baseline: 1.4300x; 1.4300x over previous
#include <cuda_runtime.h>
#include <cstdint>

// Word2DM loss via Gram-matrix identity:
//   sims(b, X) = || Bt^T X ||_F^2 = <Gt, Gx>_F,  G = B B^T (contract over m)
//   Symmetric pair coverage: thread n handles cyclic offsets d=0..9 (+10 for n<10)
//   loss_b = log1p(exp(-sims_ctx)) + sum_k log1p(exp(+sims_neg_k)); out = mean.

#define NDIM 20
#define MDIM 20
#define ROWF 400          // floats per vocab row
#define ROW4 100          // float4 per row
#define SPB  16           // samples per block
#define TPB  320          // SPB * NDIM

__global__ void w2dm_zero(float* out) { out[0] = 0.0f; }

// ---- packed f32x2 dot over 20 floats (10 FFMA2) ----
__device__ __forceinline__ float dot20(const uint64_t* __restrict__ x,
                                       const float* __restrict__ row)
{
    const ulonglong2* p = reinterpret_cast<const ulonglong2*>(row);
    uint64_t acc = 0;   // f32x2 {0,0}
    #pragma unroll
    for (int q = 0; q < 5; q++) {
        ulonglong2 v = p[q];
        asm("fma.rn.f32x2 %0, %1, %2, %3;" : "=l"(acc) : "l"(x[2*q+0]), "l"(v.x), "l"(acc));
        asm("fma.rn.f32x2 %0, %1, %2, %3;" : "=l"(acc) : "l"(x[2*q+1]), "l"(v.y), "l"(acc));
    }
    float lo, hi;
    asm("mov.b64 {%0, %1}, %2;" : "=f"(lo), "=f"(hi) : "l"(acc));
    return lo + hi;
}

__device__ __forceinline__ void cp16(float* sm, const float* g)
{
    unsigned a = (unsigned)__cvta_generic_to_shared(sm);
    asm volatile("cp.async.cg.shared.global [%0], [%1], 16;" :: "r"(a), "l"(g));
}
#define CP_COMMIT()  asm volatile("cp.async.commit_group;")
#define CP_WAIT(N)   asm volatile("cp.async.wait_group %0;" :: "n"(N))

// Stage SPB rows gathered from W into dst. idxp[ss*stride] = vocab index of sample ss.
__device__ __forceinline__ void stage_rows(float* __restrict__ dst,
                                           const float* __restrict__ W,
                                           const int* __restrict__ idxp,
                                           int stride, int tid)
{
    #pragma unroll
    for (int i = tid; i < SPB * ROW4; i += TPB) {
        const int ss = i / ROW4;
        const int e4 = i % ROW4;
        const int idx = idxp[ss * stride];
        cp16(dst + ss * ROWF + e4 * 4, W + (size_t)idx * ROWF + e4 * 4);
    }
}

__global__ __launch_bounds__(TPB) void w2dm_kernel(
    const float* __restrict__ Wt,
    const float* __restrict__ Wc,
    const int*   __restrict__ tgt,
    const int*   __restrict__ ctx,
    const int*   __restrict__ neg,
    float*       __restrict__ out,
    int batch, int kneg, float inv_batch)
{
    extern __shared__ float sm[];
    float* buf0    = sm;                       // SPB*ROWF
    float* buf1    = sm + SPB * ROWF;          // SPB*ROWF
    float* part    = sm + 2 * SPB * ROWF;      // SPB*NDIM
    float* lossbuf = part + SPB * NDIM;        // SPB
    int*   sidx    = (int*)(lossbuf + SPB);    // SPB tgt | SPB ctx | SPB*kneg neg

    const int tid = threadIdx.x;
    const int s   = tid / NDIM;
    const int n   = tid % NDIM;
    const int sample0 = blockIdx.x * SPB;

    // ---- preload all gather indices (out-of-range samples -> row 0) ----
    for (int i = tid; i < SPB * (2 + kneg); i += TPB) {
        int v;
        if (i < SPB) {
            const int smp = sample0 + i;
            v = (smp < batch) ? tgt[smp] : 0;
        } else if (i < 2 * SPB) {
            const int smp = sample0 + (i - SPB);
            v = (smp < batch) ? ctx[smp] : 0;
        } else {
            const int q = i - 2 * SPB;
            const int ss = q / kneg, kk = q % kneg;
            const int smp = sample0 + ss;
            v = (smp < batch) ? neg[(size_t)smp * kneg + kk] : 0;
        }
        sidx[i] = v;
    }
    __syncthreads();

    // ---- pipeline prologue: Bt -> buf0 (G_tgt), ctx -> buf1 (G_0) ----
    stage_rows(buf0, Wt, sidx, 1, tid);            CP_COMMIT();
    stage_rows(buf1, Wc, sidx + SPB, 1, tid);      CP_COMMIT();
    CP_WAIT(1);                      // Bt landed
    __syncthreads();

    // ---- Gt at the 11 cyclic offsets, x2-prescaled for symmetry ----
    uint64_t xr[10];
    {
        const ulonglong2* pr =
            reinterpret_cast<const ulonglong2*>(buf0 + s * ROWF + n * MDIM);
        #pragma unroll
        for (int q = 0; q < 5; q++) { ulonglong2 v = pr[q]; xr[2*q] = v.x; xr[2*q+1] = v.y; }
    }
    float gd[11];
    {
        const float* base = buf0 + s * ROWF;
        int r = n;
        #pragma unroll
        for (int d = 0; d <= 10; d++) {
            float t = dot20(xr, base + r * MDIM);
            gd[d] = d ? 2.0f * t : t;
            if (++r == NDIM) r = 0;
        }
    }
    __syncthreads();                 // all threads done reading buf0

    float loss = 0.0f;               // meaningful for tid < SPB

    // ---- phases: k=0 ctx (buf1), k odd -> buf0, k even -> buf1 ----
    for (int k = 0; k <= kneg; k++) {
        float* cur = (k & 1) ? buf0 : buf1;
        if (k < kneg) {              // prefetch neg k into the other buffer
            float* nxt = (k & 1) ? buf1 : buf0;
            stage_rows(nxt, Wc, sidx + 2 * SPB + k, kneg, tid);
            CP_COMMIT();
            CP_WAIT(1);              // phase-k group done, prefetch in flight
        } else {
            CP_WAIT(0);
        }
        __syncthreads();             // cur visible to all; prev part reads done

        // own row of cur
        const ulonglong2* pr =
            reinterpret_cast<const ulonglong2*>(cur + s * ROWF + n * MDIM);
        #pragma unroll
        for (int q = 0; q < 5; q++) { ulonglong2 v = pr[q]; xr[2*q] = v.x; xr[2*q+1] = v.y; }

        const float* base = cur + s * ROWF;
        float acc = 0.0f;
        int r = n;
        #pragma unroll
        for (int d = 0; d <= 9; d++) {
            acc = fmaf(dot20(xr, base + r * MDIM), gd[d], acc);
            if (++r == NDIM) r = 0;
        }
        if (n < 10)
            acc = fmaf(dot20(xr, base + (n + 10) * MDIM), gd[10], acc);
        part[s * NDIM + n] = acc;
        __syncthreads();             // part visible

        if (tid < SPB && (sample0 + tid) < batch) {
            float sims = 0.0f;
            #pragma unroll
            for (int i = 0; i < NDIM; i++) sims += part[tid * NDIM + i];
            loss += log1pf(expf((k == 0) ? -sims : sims));
        }
    }

    if (tid < SPB) lossbuf[tid] = loss;
    __syncthreads();
    if (tid == 0) {
        float bs = 0.0f;
        #pragma unroll
        for (int i = 0; i < SPB; i++) bs += lossbuf[i];
        atomicAdd(out, bs * inv_batch);
    }
}

extern "C" void kernel_launch(void* const* d_in, const int* in_sizes, int n_in,
                              void* d_out, int out_size)
{
    const float* Wt  = (const float*)d_in[0];
    const float* Wc  = (const float*)d_in[1];
    const int*   tgt = (const int*)d_in[2];
    const int*   ctx = (const int*)d_in[3];
    const int*   neg = (const int*)d_in[4];
    float*       out = (float*)d_out;

    const int batch = in_sizes[2];
    const int kneg  = in_sizes[4] / batch;
    const float inv_batch = 1.0f / (float)batch;

    const int smem_bytes =
        (2 * SPB * ROWF + SPB * NDIM + SPB) * (int)sizeof(float)
        + SPB * (2 + kneg) * (int)sizeof(int);

    cudaFuncSetAttribute(w2dm_kernel,
                         cudaFuncAttributeMaxDynamicSharedMemorySize, smem_bytes);

    w2dm_zero<<<1, 1>>>(out);

    const int grid = (batch + SPB - 1) / SPB;
    w2dm_kernel<<<grid, TPB, smem_bytes>>>(Wt, Wc, tgt, ctx, neg, out,
                                           batch, kneg, inv_batch);
}

// round 3
// speedup vs baseline: 2.5619x; 1.7916x over previous
#include <cuda_runtime.h>
#include <cstdint>

// Word2DM loss, Gram identity: sims = sum_{a<=b} w_ab * Gt[a,b] * Gx[a,b],
// w = 1 diag / 2 off-diag.  Rows grouped 5x4; 10 roles each own one group
// (registers) and stream one foreign group (smem), x2 threads splitting the
// m-dimension in halves. Gt halves combined once via shfl_xor.

#define NDIM 20
#define ROWF 400
#define ROW4 100
#define SPB  16
#define TPS  20                 // threads per sample: 10 roles x 2 halves
#define TPB  (SPB * TPS)        // 320
#define GSTRIDE 84              // words per 4-row group (4*20 + 4 pad)
#define SSTRIDE 424             // words per sample tile (5*84 + 4 pad)

__global__ void w2dm_zero(float* out) { out[0] = 0.0f; }

__device__ __forceinline__ float red2(uint64_t v) {
    float lo, hi; asm("mov.b64 {%0,%1},%2;" : "=f"(lo), "=f"(hi) : "l"(v));
    return lo + hi;
}
__device__ __forceinline__ uint64_t ffma2(uint64_t a, uint64_t b, uint64_t c) {
    uint64_t r; asm("fma.rn.f32x2 %0,%1,%2,%3;" : "=l"(r) : "l"(a), "l"(b), "l"(c));
    return r;
}
__device__ __forceinline__ float dot5(const uint64_t* x, const uint64_t* y) {
    uint64_t acc = 0;
    #pragma unroll
    for (int q = 0; q < 5; q++) acc = ffma2(x[q], y[q], acc);
    return red2(acc);
}

__device__ __forceinline__ void cp16(float* smp, const float* g) {
    unsigned a = (unsigned)__cvta_generic_to_shared(smp);
    asm volatile("cp.async.cg.shared.global [%0], [%1], 16;" :: "r"(a), "l"(g));
}
#define CP_COMMIT()  asm volatile("cp.async.commit_group;")
#define CP_WAIT(N)   asm volatile("cp.async.wait_group %0;" :: "n"(N))

// Gather SPB rows of W into padded tile layout.
__device__ __forceinline__ void stage_rows(float* __restrict__ dst,
                                           const float* __restrict__ W,
                                           const int* __restrict__ idxp,
                                           int stride, int tid)
{
    #pragma unroll
    for (int i = tid; i < SPB * ROW4; i += TPB) {
        const int ss = i / ROW4;
        const int e4 = i % ROW4;
        const int n  = e4 / 5;
        const int j  = e4 % 5;
        const int idx = idxp[ss * stride];
        cp16(dst + ss * SSTRIDE + (n >> 2) * GSTRIDE + (n & 3) * 20 + j * 4,
             W + (size_t)idx * ROWF + e4 * 4);
    }
}

__global__ __launch_bounds__(TPB, 2) void w2dm_kernel(
    const float* __restrict__ Wt,
    const float* __restrict__ Wc,
    const int*   __restrict__ tgt,
    const int*   __restrict__ ctx,
    const int*   __restrict__ neg,
    float*       __restrict__ out,
    int batch, int kneg, float inv_batch)
{
    extern __shared__ float sm[];
    float* buf0    = sm;                         // SPB*SSTRIDE
    float* buf1    = sm + SPB * SSTRIDE;
    float* part    = sm + 2 * SPB * SSTRIDE;     // SPB*TPS
    float* lossbuf = part + SPB * TPS;           // SPB
    int*   sidx    = (int*)(lossbuf + SPB);      // SPB*(2+kneg)

    const int tid  = threadIdx.x;
    const int s    = tid / TPS;
    const int p    = tid % TPS;
    const int role = p >> 1;
    const int h    = p & 1;
    const int gown = role % 5;
    const int gfor = (role + 1 + (role >= 5 ? 1 : 0)) % 5;
    const int sample0 = blockIdx.x * SPB;

    // u64 indices within a sample tile (word/2)
    const int ob  = gown * 42 + 5 * h;   // own group, this half
    const int fb0 = gfor * 42 + 5 * h;   // foreign group, this half

    // ---- preload gather indices ----
    for (int i = tid; i < SPB * (2 + kneg); i += TPB) {
        int v;
        if (i < SPB) {
            const int smp = sample0 + i;
            v = (smp < batch) ? tgt[smp] : 0;
        } else if (i < 2 * SPB) {
            const int smp = sample0 + (i - SPB);
            v = (smp < batch) ? ctx[smp] : 0;
        } else {
            const int q = i - 2 * SPB;
            const int smp = sample0 + q / kneg;
            v = (smp < batch) ? neg[(size_t)smp * kneg + (q % kneg)] : 0;
        }
        sidx[i] = v;
    }
    __syncthreads();

    // ---- pipeline prologue ----
    stage_rows(buf0, Wt, sidx, 1, tid);        CP_COMMIT();   // Bt
    stage_rows(buf1, Wc, sidx + SPB, 1, tid);  CP_COMMIT();   // ctx
    CP_WAIT(1);
    __syncthreads();

    // ---- Gt: 21 weighted pair values (halves combined via shfl) ----
    uint64_t o[4][5];
    float gts[21];
    {
        const uint64_t* tb = (const uint64_t*)(buf0 + s * SSTRIDE);
        #pragma unroll
        for (int a = 0; a < 4; a++)
            #pragma unroll
            for (int q = 0; q < 5; q++) o[a][q] = tb[ob + a * 10 + q];

        #pragma unroll
        for (int fb = 0; fb < 4; fb++) {
            uint64_t f[5];
            #pragma unroll
            for (int q = 0; q < 5; q++) f[q] = tb[fb0 + fb * 10 + q];
            #pragma unroll
            for (int a = 0; a < 4; a++) gts[fb * 4 + a] = dot5(o[a], f);
        }
        if (role < 5) {
            gts[16] = dot5(o[0], o[0]); gts[17] = dot5(o[0], o[1]);
            gts[18] = dot5(o[0], o[2]); gts[19] = dot5(o[0], o[3]);
            gts[20] = dot5(o[1], o[1]);
        } else {
            gts[16] = dot5(o[1], o[2]); gts[17] = dot5(o[1], o[3]);
            gts[18] = dot5(o[2], o[2]); gts[19] = dot5(o[2], o[3]);
            gts[20] = dot5(o[3], o[3]);
        }
        #pragma unroll
        for (int i = 0; i < 16; i++) {
            float fu = gts[i] + __shfl_xor_sync(0xffffffffu, gts[i], 1);
            gts[i] = 2.0f * fu;
        }
        const bool A = (role < 5);
        const float w0 = A ? 1.f : 2.f, w2 = A ? 2.f : 1.f;
        const float wv[5] = { w0, 2.f, w2, 2.f, 1.f };
        #pragma unroll
        for (int i = 0; i < 5; i++) {
            float fu = gts[16 + i] + __shfl_xor_sync(0xffffffffu, gts[16 + i], 1);
            gts[16 + i] = wv[i] * fu;
        }
    }
    __syncthreads();   // all threads done reading buf0

    float loss = 0.0f;  // meaningful for tid < SPB

    // ---- phases: k=0 ctx (buf1), then negs alternating buffers ----
    for (int k = 0; k <= kneg; k++) {
        float* cur = (k & 1) ? buf0 : buf1;
        if (k < kneg) {
            float* nxt = (k & 1) ? buf1 : buf0;
            stage_rows(nxt, Wc, sidx + 2 * SPB + k, kneg, tid);
            CP_COMMIT();
            CP_WAIT(1);
        } else {
            CP_WAIT(0);
        }
        __syncthreads();

        const uint64_t* tb = (const uint64_t*)(cur + s * SSTRIDE);
        #pragma unroll
        for (int a = 0; a < 4; a++)
            #pragma unroll
            for (int q = 0; q < 5; q++) o[a][q] = tb[ob + a * 10 + q];

        float acc = 0.0f;
        #pragma unroll
        for (int fb = 0; fb < 4; fb++) {
            uint64_t f[5];
            #pragma unroll
            for (int q = 0; q < 5; q++) f[q] = tb[fb0 + fb * 10 + q];
            #pragma unroll
            for (int a = 0; a < 4; a++)
                acc = fmaf(dot5(o[a], f), gts[fb * 4 + a], acc);
        }
        if (role < 5) {
            acc = fmaf(dot5(o[0], o[0]), gts[16], acc);
            acc = fmaf(dot5(o[0], o[1]), gts[17], acc);
            acc = fmaf(dot5(o[0], o[2]), gts[18], acc);
            acc = fmaf(dot5(o[0], o[3]), gts[19], acc);
            acc = fmaf(dot5(o[1], o[1]), gts[20], acc);
        } else {
            acc = fmaf(dot5(o[1], o[2]), gts[16], acc);
            acc = fmaf(dot5(o[1], o[3]), gts[17], acc);
            acc = fmaf(dot5(o[2], o[2]), gts[18], acc);
            acc = fmaf(dot5(o[2], o[3]), gts[19], acc);
            acc = fmaf(dot5(o[3], o[3]), gts[20], acc);
        }
        part[s * TPS + p] = acc;
        __syncthreads();

        if (tid < SPB && (sample0 + tid) < batch) {
            float sims = 0.0f;
            #pragma unroll
            for (int i = 0; i < TPS; i++) sims += part[tid * TPS + i];
            loss += log1pf(expf((k == 0) ? -sims : sims));
        }
    }

    if (tid < SPB) lossbuf[tid] = loss;
    __syncthreads();
    if (tid == 0) {
        float bs = 0.0f;
        #pragma unroll
        for (int i = 0; i < SPB; i++) bs += lossbuf[i];
        atomicAdd(out, bs * inv_batch);
    }
}

extern "C" void kernel_launch(void* const* d_in, const int* in_sizes, int n_in,
                              void* d_out, int out_size)
{
    const float* Wt  = (const float*)d_in[0];
    const float* Wc  = (const float*)d_in[1];
    const int*   tgt = (const int*)d_in[2];
    const int*   ctx = (const int*)d_in[3];
    const int*   neg = (const int*)d_in[4];
    float*       out = (float*)d_out;

    const int batch = in_sizes[2];
    const int kneg  = in_sizes[4] / batch;
    const float inv_batch = 1.0f / (float)batch;

    const int smem_bytes =
        (2 * SPB * SSTRIDE + SPB * TPS + SPB) * (int)sizeof(float)
        + SPB * (2 + kneg) * (int)sizeof(int);

    cudaFuncSetAttribute(w2dm_kernel,
                         cudaFuncAttributeMaxDynamicSharedMemorySize, smem_bytes);

    w2dm_zero<<<1, 1>>>(out);

    const int grid = (batch + SPB - 1) / SPB;
    w2dm_kernel<<<grid, TPB, smem_bytes>>>(Wt, Wc, tgt, ctx, neg, out,
                                           batch, kneg, inv_batch);
}